// round 2
// baseline (speedup 1.0000x reference)
#include <cuda_runtime.h>
#include <math.h>

// Problem constants (fixed by the reference)
#define T  1024
#define B  256
#define H  20

// Memory kernel me[t] = sigmoid(MLP(t)), produced by mlp_kernel, consumed by solver_kernel.
__device__ float g_me[T];

// ---------------------------------------------------------------------------
// Kernel 1: tiny MLP over the T time points. One thread per time point.
// ---------------------------------------------------------------------------
__global__ void mlp_kernel(const float* __restrict__ t,
                           const float* __restrict__ w1, const float* __restrict__ b1,
                           const float* __restrict__ w2, const float* __restrict__ b2,
                           const float* __restrict__ w3, const float* __restrict__ b3,
                           const float* __restrict__ w4, const float* __restrict__ b4)
{
    int i = blockIdx.x * blockDim.x + threadIdx.x;
    if (i >= T) return;
    float x = t[i];

    float h1[H], h2[H], h3[H];
#pragma unroll
    for (int j = 0; j < H; ++j) h1[j] = tanhf(x * w1[j] + b1[j]);

#pragma unroll
    for (int j = 0; j < H; ++j) {
        float s = b2[j];
#pragma unroll
        for (int k = 0; k < H; ++k) s += h1[k] * w2[k * H + j];
        h2[j] = tanhf(s);
    }

#pragma unroll
    for (int j = 0; j < H; ++j) {
        float s = b3[j];
#pragma unroll
        for (int k = 0; k < H; ++k) s += h2[k] * w3[k * H + j];
        h3[j] = tanhf(s);
    }

    float s = b4[0];
#pragma unroll
    for (int k = 0; k < H; ++k) s += h3[k] * w4[k];

    g_me[i] = 1.0f / (1.0f + expf(-s));   // sigmoid
}

// ---------------------------------------------------------------------------
// Kernel 2: sequential integro-ODE. One WARP per batch element (batch elements
// are fully independent). History I_hist[:,b] lives in shared memory (4KB/warp).
// Per step: lanes split the history dot product, butterfly-reduce, all lanes
// redundantly apply the SIR update, owner lane appends new I to history.
// Only __syncwarp() needed — no block/grid barriers in the main loop.
// ---------------------------------------------------------------------------
__global__ void solver_kernel(const float* __restrict__ t,
                              const float* __restrict__ y,
                              const float* __restrict__ beta_p,
                              const float* __restrict__ gamma_p,
                              float* __restrict__ out)
{
    __shared__ float me_s[T + 32];   // padded with zeros: tail of the shifting window
    __shared__ float ih_s[4][T];     // per-warp I history (zero-initialized)

    const int tid  = threadIdx.x;
    const int w    = tid >> 5;
    const int lane = tid & 31;

    // Cooperative init: me (+ zero pad) and zeroed history.
    for (int i = tid; i < T + 32; i += 128) me_s[i] = (i < T) ? g_me[i] : 0.0f;
    for (int i = tid; i < 4 * T; i += 128) (&ih_s[0][0])[i] = 0.0f;
    __syncthreads();

    const int b = blockIdx.x * 4 + w;          // 64 blocks * 4 warps = 256 batch
    const float dt    = t[0] - t[1];           // = 1/(T-1), positive
    const float beta  = beta_p[0];
    const float gamma = gamma_p[0];

    // y has shape (B, 1, 3)
    float S = y[b * 3 + 0];
    float I = y[b * 3 + 1];
    float R = y[b * 3 + 2];

    float* ihw = ih_s[w];
    if (lane == 0) ihw[0] = I;

    // solution[0] = y0 ; diff[T-1] = 0  (d_out is poisoned, must write)
    {
        float sv = (lane == 0) ? S : ((lane == 1) ? I : R);
        if (lane < 3) {
            out[b * 3 + lane] = sv;
            out[T * B * 3 + (T - 1) * (B * 3) + b * 3 + lane] = 0.0f;
        }
    }
    __syncwarp();

    for (int idx = 0; idx < T - 1; ++idx) {
        const int off   = (T - 1) - idx;       // me window start
        const int nIter = (idx >> 5) + 1;      // lanes cover t = 32*j + lane <= idx

        const float* mp = me_s + off + lane;
        const float* ip = ihw + lane;
        float acc = 0.0f;
        // Tail iterations with t > idx read me pad (=0) and zeroed history -> contribute 0.
#pragma unroll 4
        for (int j = 0; j < nIter; ++j)
            acc += mp[j * 32] * ip[j * 32];

        // Butterfly reduce: every lane ends with the full sum.
#pragma unroll
        for (int s = 16; s > 0; s >>= 1)
            acc += __shfl_xor_sync(0xffffffffu, acc, s);

        const float integ = dt * acc;
        const float bSI = beta * S * I;
        const float gI  = gamma * I;
        const float dS  = integ - bSI;
        const float dI  = bSI - gI;
        const float dR  = gI - integ;
        S += dS * dt;
        I += dI * dt;
        R += dR * dt;

        const float sv = (lane == 0) ? S  : ((lane == 1) ? I  : R);
        const float dv = (lane == 0) ? dS : ((lane == 1) ? dI : dR);
        if (lane < 3) {
            out[(idx + 1) * (B * 3) + b * 3 + lane] = sv;            // solution[idx+1]
            out[T * B * 3 + idx * (B * 3) + b * 3 + lane] = dv;      // diff[idx]
        }
        if (lane == 0) ihw[idx + 1] = I;   // append I_hist[idx+1]
        __syncwarp();
    }
}

// ---------------------------------------------------------------------------
// Launch: two kernels, stream-ordered, graph-capturable, allocation-free.
// Input order (metadata): t, y, w1, b1, w2, b2, w3, b3, w4, b4, beta, gamma
// Output: [solution (T,B,3) | diff (T,B,3)] float32
// ---------------------------------------------------------------------------
extern "C" void kernel_launch(void* const* d_in, const int* in_sizes, int n_in,
                              void* d_out, int out_size)
{
    const float* t  = (const float*)d_in[0];
    const float* y  = (const float*)d_in[1];
    const float* w1 = (const float*)d_in[2];
    const float* b1 = (const float*)d_in[3];
    const float* w2 = (const float*)d_in[4];
    const float* b2 = (const float*)d_in[5];
    const float* w3 = (const float*)d_in[6];
    const float* b3 = (const float*)d_in[7];
    const float* w4 = (const float*)d_in[8];
    const float* b4 = (const float*)d_in[9];
    const float* be = (const float*)d_in[10];
    const float* ga = (const float*)d_in[11];
    float* out = (float*)d_out;

    mlp_kernel<<<4, 256>>>(t, w1, b1, w2, b2, w3, b3, w4, b4);
    solver_kernel<<<64, 128>>>(t, y, be, ga, out);
}

// round 3
// speedup vs baseline: 1.5348x; 1.5348x over previous
#include <cuda_runtime.h>
#include <math.h>

// Problem constants (fixed by the reference)
#define T  1024
#define B  256
#define H  20

// Memory kernel me[t] = sigmoid(MLP(t)), produced by mlp_kernel, consumed by solver_kernel.
__device__ float g_me[T];

// ---------------------------------------------------------------------------
// Kernel 1: tiny MLP over the T time points. One thread per time point.
// ---------------------------------------------------------------------------
__global__ void mlp_kernel(const float* __restrict__ t,
                           const float* __restrict__ w1, const float* __restrict__ b1,
                           const float* __restrict__ w2, const float* __restrict__ b2,
                           const float* __restrict__ w3, const float* __restrict__ b3,
                           const float* __restrict__ w4, const float* __restrict__ b4)
{
    int i = blockIdx.x * blockDim.x + threadIdx.x;
    if (i >= T) return;
    float x = t[i];

    float h1[H], h2[H], h3[H];
#pragma unroll
    for (int j = 0; j < H; ++j) h1[j] = tanhf(x * w1[j] + b1[j]);

#pragma unroll
    for (int j = 0; j < H; ++j) {
        float s = b2[j];
#pragma unroll
        for (int k = 0; k < H; ++k) s += h1[k] * w2[k * H + j];
        h2[j] = tanhf(s);
    }

#pragma unroll
    for (int j = 0; j < H; ++j) {
        float s = b3[j];
#pragma unroll
        for (int k = 0; k < H; ++k) s += h2[k] * w3[k * H + j];
        h3[j] = tanhf(s);
    }

    float s = b4[0];
#pragma unroll
    for (int k = 0; k < H; ++k) s += h3[k] * w4[k];

    g_me[i] = 1.0f / (1.0f + expf(-s));   // sigmoid
}

// ---------------------------------------------------------------------------
// Kernel 2: chunked sequential integro-ODE. ONE WARP per batch element,
// one block per batch (256 blocks -> spread across all SMs).
//
// integ[n] = Sum_{l=0..n} rk[l] * I_hist[n-l],  rk[l] = me[T-1-l].
//
// Chunk of 32 steps at base b0:
//   FAR:  lane l computes far_l = Sum_{t<b0} rk[b0+l-t]*I_hist[t]
//         (parallel, pipelined, float4-vectorized broadcast of I_hist)
//   NEAR: at inner step s, lanes l>=s add rk[l-s]*I_cur (I replicated in
//         registers); lane s's acc is then complete -> single uniform SHFL
//         broadcast; all lanes redundantly advance (S, I, R).
// Only __syncwarp at chunk boundaries (orders lane0's I_hist stores).
// ---------------------------------------------------------------------------
__global__ void solver_kernel(const float* __restrict__ t,
                              const float* __restrict__ y,
                              const float* __restrict__ beta_p,
                              const float* __restrict__ gamma_p,
                              float* __restrict__ out)
{
    __shared__ __align__(16) float rkp[32 + T]; // rkp[32+m] = me[T-1-m]; rkp[0..31]=0 pad
    __shared__ __align__(16) float ih[T];       // I history for this batch element

    const int lane = threadIdx.x;   // blockDim.x == 32

    // Init: reversed kernel (+ zero pad for negative lags), zeroed history.
    rkp[lane] = 0.0f;
    for (int m = lane; m < T; m += 32) rkp[32 + m] = g_me[T - 1 - m];
    for (int i = lane; i < T; i += 32) ih[i] = 0.0f;
    __syncwarp();

    const int   b     = blockIdx.x;
    const float dt    = t[0] - t[1];       // = 1/(T-1), positive
    const float beta  = beta_p[0];
    const float gamma = gamma_p[0];

    // y has shape (B, 1, 3); state replicated in every lane.
    float S = y[b * 3 + 0];
    float I = y[b * 3 + 1];
    float R = y[b * 3 + 2];

    if (lane == 0) ih[0] = I;

    // solution[0] = y0 ; diff[T-1] = 0 (d_out is poisoned -> must be written)
    if (lane < 3) {
        float sv = (lane == 0) ? S : ((lane == 1) ? I : R);
        out[b * 3 + lane] = sv;
        out[T * B * 3 + (T - 1) * (B * 3) + b * 3 + lane] = 0.0f;
    }
    __syncwarp();

    const float* rk  = rkp + 32;
    const float* rkl = rk + lane;          // near-term kernel taps: rkl[-s] = rk[lane-s]

    for (int c = 0; c < 32; ++c) {
        const int base = c << 5;

        // ---- FAR: dot of old history with this lane's shifted kernel ----
        float a0 = 0.0f, a1 = 0.0f, a2 = 0.0f, a3 = 0.0f;
        {
            const float*  rf  = rk + base + lane;     // rf[-t] = rk[base+lane-t]
            const float4* ih4 = (const float4*)ih;    // broadcast reads
            const int n4 = base >> 2;
#pragma unroll 4
            for (int q = 0; q < n4; ++q) {
                const float4 iv = ih4[q];
                const int tq = q << 2;
                a0 = fmaf(rf[-tq],       iv.x, a0);
                a1 = fmaf(rf[-(tq + 1)], iv.y, a1);
                a2 = fmaf(rf[-(tq + 2)], iv.z, a2);
                a3 = fmaf(rf[-(tq + 3)], iv.w, a3);
            }
        }
        float acc = (a0 + a1) + (a2 + a3);

        // ---- NEAR: 32 sequential steps, one SHFL each ----
#pragma unroll
        for (int s = 0; s < 32; ++s) {
            const int idx = base + s;                 // global step index
            // lanes l<s hit the zero pad (rkp[<32]) -> contribute 0
            acc = fmaf(rkl[-s], I, acc);
            const float a = __shfl_sync(0xffffffffu, acc, s);

            const float integ = dt * a;
            const float bSI   = beta * S * I;
            const float gI    = gamma * I;
            const float dS    = integ - bSI;
            const float dI    = bSI - gI;
            const float dR    = gI - integ;

            if (idx < T - 1) {                        // last chunk has 31 steps
                S = fmaf(dS, dt, S);
                I = fmaf(dI, dt, I);
                R = fmaf(dR, dt, R);

                if (lane < 3) {
                    const float sv = (lane == 0) ? S  : ((lane == 1) ? I  : R);
                    const float dv = (lane == 0) ? dS : ((lane == 1) ? dI : dR);
                    out[(idx + 1) * (B * 3) + b * 3 + lane] = sv;          // solution
                    out[T * B * 3 + idx * (B * 3) + b * 3 + lane] = dv;    // diff
                }
                if (lane == 0) ih[idx + 1] = I;
            }
        }
        __syncwarp();   // order lane0's ih stores before next chunk's FAR reads
    }
}

// ---------------------------------------------------------------------------
// Launch: two kernels, stream-ordered, graph-capturable, allocation-free.
// Input order (metadata): t, y, w1, b1, w2, b2, w3, b3, w4, b4, beta, gamma
// Output: [solution (T,B,3) | diff (T,B,3)] float32
// ---------------------------------------------------------------------------
extern "C" void kernel_launch(void* const* d_in, const int* in_sizes, int n_in,
                              void* d_out, int out_size)
{
    const float* t  = (const float*)d_in[0];
    const float* y  = (const float*)d_in[1];
    const float* w1 = (const float*)d_in[2];
    const float* b1 = (const float*)d_in[3];
    const float* w2 = (const float*)d_in[4];
    const float* b2 = (const float*)d_in[5];
    const float* w3 = (const float*)d_in[6];
    const float* b3 = (const float*)d_in[7];
    const float* w4 = (const float*)d_in[8];
    const float* b4 = (const float*)d_in[9];
    const float* be = (const float*)d_in[10];
    const float* ga = (const float*)d_in[11];
    float* out = (float*)d_out;

    mlp_kernel<<<4, 256>>>(t, w1, b1, w2, b2, w3, b3, w4, b4);
    solver_kernel<<<B, 32>>>(t, y, be, ga, out);
}

// round 4
// speedup vs baseline: 1.9984x; 1.3020x over previous
#include <cuda_runtime.h>
#include <math.h>

// Problem constants (fixed by the reference)
#define T  1024
#define B  256
#define H  20
#define FULL 0xffffffffu
#define OSTRIDE (B * 3)          // 768 floats between consecutive time rows

// Memory kernel me[t] = sigmoid(MLP(t))
__device__ float g_me[T];

// ---------------------------------------------------------------------------
// Kernel 1: tiny MLP over the T time points. One thread per time point.
// ---------------------------------------------------------------------------
__global__ void mlp_kernel(const float* __restrict__ t,
                           const float* __restrict__ w1, const float* __restrict__ b1,
                           const float* __restrict__ w2, const float* __restrict__ b2,
                           const float* __restrict__ w3, const float* __restrict__ b3,
                           const float* __restrict__ w4, const float* __restrict__ b4)
{
    int i = blockIdx.x * blockDim.x + threadIdx.x;
    if (i >= T) return;
    float x = t[i];

    float h1[H], h2[H], h3[H];
#pragma unroll
    for (int j = 0; j < H; ++j) h1[j] = tanhf(x * w1[j] + b1[j]);

#pragma unroll
    for (int j = 0; j < H; ++j) {
        float s = b2[j];
#pragma unroll
        for (int k = 0; k < H; ++k) s += h1[k] * w2[k * H + j];
        h2[j] = tanhf(s);
    }

#pragma unroll
    for (int j = 0; j < H; ++j) {
        float s = b3[j];
#pragma unroll
        for (int k = 0; k < H; ++k) s += h2[k] * w3[k * H + j];
        h3[j] = tanhf(s);
    }

    float s = b4[0];
#pragma unroll
    for (int k = 0; k < H; ++k) s += h3[k] * w4[k];

    g_me[i] = 1.0f / (1.0f + expf(-s));   // sigmoid
}

// ---------------------------------------------------------------------------
// Kernel 2: one block (128 threads) per batch element.
//   warp 0   : sequential near chain (32-step chunks), branch-free body,
//              kernel taps + recent history in registers.
//   warps 1-3: compute the old-history far dot for chunk c+1 while warp 0
//              runs chunk c (double-buffered via smem farbuf).
//
// integ[n] = Sum_{l<=n} rk[l] * I_hist[n-l],  rk[l] = me[T-1-l].
// Chunk c (base=32c) accumulator before its near phase:
//   acc_lane = Sum_{t<32(c-1)} rk[32c+lane-t] * ih[t]        (helpers, smem)
//            + Sum_{u=0..31}   rk[lane+32-u]  * Ir[u]        (registers)
// Near step s: acc += rk[lane-s]*I ; lane s's acc broadcast -> state update.
// ---------------------------------------------------------------------------
__global__ void __launch_bounds__(128, 1)
solver_kernel(const float* __restrict__ t,
              const float* __restrict__ y,
              const float* __restrict__ beta_p,
              const float* __restrict__ gamma_p,
              float* __restrict__ out)
{
    __shared__ __align__(16) float rkp[32 + T]; // rkp[32+m] = me[T-1-m]; rkp[0..31]=0 pad
    __shared__ __align__(16) float ih[T];       // I history (ih[t] = I_t)
    __shared__ float farbuf[2][3][32];          // double-buffered helper partials

    const int tid  = threadIdx.x;
    const int w    = tid >> 5;
    const int lane = tid & 31;

    // Cooperative init
    for (int i = tid; i < 32 + T; i += 128) rkp[i] = (i < 32) ? 0.0f : g_me[T - 1 - (i - 32)];
    for (int i = tid; i < T; i += 128)      ih[i] = 0.0f;
    if (tid < 2 * 3 * 32)                   (&farbuf[0][0][0])[tid] = 0.0f;

    const int   b     = blockIdx.x;
    const float dt    = t[0] - t[1];       // = 1/(T-1), positive
    const float beta  = beta_p[0];
    const float gamma = gamma_p[0];

    // State replicated in every lane of warp 0 (harmlessly in helpers too).
    float S = y[b * 3 + 0];
    float I = y[b * 3 + 1];
    float R = y[b * 3 + 2];

    if (tid == 0) ih[0] = I;

    // solution[0] = y0 ; diff[T-1] = 0 (d_out is poisoned -> must be written)
    if (w == 0 && lane < 3) {
        float sv = (lane == 0) ? S : ((lane == 1) ? I : R);
        out[b * 3 + lane] = sv;
        out[(size_t)T * OSTRIDE + (T - 1) * OSTRIDE + b * 3 + lane] = 0.0f;
    }
    __syncthreads();

    const float* rk = rkp + 32;

    // Register-resident kernel taps (warp 0 uses them; cheap everywhere).
    float tap[32], tapR[32];
#pragma unroll
    for (int s = 0; s < 32; ++s) tap[s]  = rkp[32 + lane - s];   // rk[lane-s], pad=0 for lane<s
#pragma unroll
    for (int u = 0; u < 32; ++u) tapR[u] = rk[lane + 32 - u];    // rk[lane+32-u]

    float Ir[32];                         // previous chunk's I values (pre-update)
#pragma unroll
    for (int u = 0; u < 32; ++u) Ir[u] = 0.0f;

    float* po_sol = out + b * 3 + lane;                       // solution rows
    float* po_dif = out + (size_t)T * OSTRIDE + b * 3 + lane; // diff rows

    // ---------------- main loop: chunks 0..30 (full 32 steps each) ----------
    for (int c = 0; c < 31; ++c) {
        if (w == 0) {
            const int base = c << 5;
            // accumulate far part: helper buffer + register-recent history
            float acc = farbuf[c & 1][0][lane] + farbuf[c & 1][1][lane]
                      + farbuf[c & 1][2][lane];
#pragma unroll
            for (int u = 0; u < 32; ++u) acc = fmaf(tapR[u], Ir[u], acc);

            float* ps = po_sol + base * OSTRIDE;
            float* pd = po_dif + base * OSTRIDE;

#pragma unroll
            for (int s = 0; s < 32; ++s) {
                Ir[s] = I;                                  // ih[base+s]
                acc = fmaf(tap[s], I, acc);
                const float a     = __shfl_sync(FULL, acc, s);
                const float integ = dt * a;
                const float bSI   = beta * S * I;
                const float gI    = gamma * I;
                const float dS    = integ - bSI;
                const float dI    = bSI - gI;
                const float dR    = gI - integ;
                S = fmaf(dS, dt, S);
                I = fmaf(dI, dt, I);
                R = fmaf(dR, dt, R);
                const float sv = (lane == 0) ? S  : ((lane == 1) ? I  : R);
                const float dv = (lane == 0) ? dS : ((lane == 1) ? dI : dR);
                if (lane < 3) ps[(s + 1) * OSTRIDE] = sv;   // predicated STG
                if (lane < 3) pd[s * OSTRIDE]       = dv;   // predicated STG
                ih[base + s + 1] = I;                       // all lanes, same addr: collapses
            }
        } else {
            // Helpers: farOld for chunk c+1 over history t < 32c.
            const int hw = w - 1;                           // 0..2
            float h0 = 0.0f, h1 = 0.0f, h2 = 0.0f, h3 = 0.0f;
            const float*  rf  = rk + ((c + 1) << 5) + lane; // rf[-t] = rk[32(c+1)+lane-t]
            const float4* ih4 = (const float4*)ih;
            const int n4 = (c << 5) >> 2;                   // 8c float4 groups
            for (int q = hw; q < n4; q += 3) {
                const float4 iv = ih4[q];
                const int tq = q << 2;
                h0 = fmaf(rf[-tq],       iv.x, h0);
                h1 = fmaf(rf[-(tq + 1)], iv.y, h1);
                h2 = fmaf(rf[-(tq + 2)], iv.z, h2);
                h3 = fmaf(rf[-(tq + 3)], iv.w, h3);
            }
            farbuf[(c + 1) & 1][hw][lane] = (h0 + h1) + (h2 + h3);
        }
        __syncthreads();   // farbuf handoff + ih visibility for next chunk
    }

    // ---------------- final chunk c=31: steps 992..1022 (31 steps) ----------
    if (w == 0) {
        const int base = 31 << 5;   // 992, compile-time
        float acc = farbuf[1][0][lane] + farbuf[1][1][lane] + farbuf[1][2][lane];
#pragma unroll
        for (int u = 0; u < 32; ++u) acc = fmaf(tapR[u], Ir[u], acc);

        float* ps = po_sol + base * OSTRIDE;
        float* pd = po_dif + base * OSTRIDE;

#pragma unroll
        for (int s = 0; s < 31; ++s) {
            acc = fmaf(tap[s], I, acc);
            const float a     = __shfl_sync(FULL, acc, s);
            const float integ = dt * a;
            const float bSI   = beta * S * I;
            const float gI    = gamma * I;
            const float dS    = integ - bSI;
            const float dI    = bSI - gI;
            const float dR    = gI - integ;
            S = fmaf(dS, dt, S);
            I = fmaf(dI, dt, I);
            R = fmaf(dR, dt, R);
            const float sv = (lane == 0) ? S  : ((lane == 1) ? I  : R);
            const float dv = (lane == 0) ? dS : ((lane == 1) ? dI : dR);
            if (lane < 3) ps[(s + 1) * OSTRIDE] = sv;
            if (lane < 3) pd[s * OSTRIDE]       = dv;
        }
    }
}

// ---------------------------------------------------------------------------
// Launch: two kernels, stream-ordered, graph-capturable, allocation-free.
// Input order (metadata): t, y, w1, b1, w2, b2, w3, b3, w4, b4, beta, gamma
// Output: [solution (T,B,3) | diff (T,B,3)] float32
// ---------------------------------------------------------------------------
extern "C" void kernel_launch(void* const* d_in, const int* in_sizes, int n_in,
                              void* d_out, int out_size)
{
    const float* t  = (const float*)d_in[0];
    const float* y  = (const float*)d_in[1];
    const float* w1 = (const float*)d_in[2];
    const float* b1 = (const float*)d_in[3];
    const float* w2 = (const float*)d_in[4];
    const float* b2 = (const float*)d_in[5];
    const float* w3 = (const float*)d_in[6];
    const float* b3 = (const float*)d_in[7];
    const float* w4 = (const float*)d_in[8];
    const float* b4 = (const float*)d_in[9];
    const float* be = (const float*)d_in[10];
    const float* ga = (const float*)d_in[11];
    float* out = (float*)d_out;

    mlp_kernel<<<4, 256>>>(t, w1, b1, w2, b2, w3, b3, w4, b4);
    solver_kernel<<<B, 128>>>(t, y, be, ga, out);
}

// round 7
// speedup vs baseline: 2.0727x; 1.0372x over previous
#include <cuda_runtime.h>
#include <math.h>

// Problem constants (fixed by the reference)
#define T  1024
#define B  256
#define H  20
#define FULL 0xffffffffu
#define OSTRIDE (B * 3)          // 768 floats between consecutive time rows

// Memory kernel me[t] = sigmoid(MLP(t))
__device__ float g_me[T];

// ---------------------------------------------------------------------------
// Kernel 1: tiny MLP over the T time points. One thread per time point.
// ---------------------------------------------------------------------------
__global__ void mlp_kernel(const float* __restrict__ t,
                           const float* __restrict__ w1, const float* __restrict__ b1,
                           const float* __restrict__ w2, const float* __restrict__ b2,
                           const float* __restrict__ w3, const float* __restrict__ b3,
                           const float* __restrict__ w4, const float* __restrict__ b4)
{
    int i = blockIdx.x * blockDim.x + threadIdx.x;
    if (i >= T) return;
    float x = t[i];

    float h1[H], h2[H], h3[H];
#pragma unroll
    for (int j = 0; j < H; ++j) h1[j] = tanhf(x * w1[j] + b1[j]);

#pragma unroll
    for (int j = 0; j < H; ++j) {
        float s = b2[j];
#pragma unroll
        for (int k = 0; k < H; ++k) s += h1[k] * w2[k * H + j];
        h2[j] = tanhf(s);
    }

#pragma unroll
    for (int j = 0; j < H; ++j) {
        float s = b3[j];
#pragma unroll
        for (int k = 0; k < H; ++k) s += h2[k] * w3[k * H + j];
        h3[j] = tanhf(s);
    }

    float s = b4[0];
#pragma unroll
    for (int k = 0; k < H; ++k) s += h3[k] * w4[k];

    g_me[i] = 1.0f / (1.0f + expf(-s));   // sigmoid
}

// ---------------------------------------------------------------------------
// Kernel 2: one block (128 threads) per batch element.
//   warp 0   : near chain, 32-step chunks, with 4-step LOOKAHEAD broadcast:
//              shfl for step j issued at step j-4; each lane redundantly adds
//              the last 4 near taps (rq0..rq3, replicated scalars) via a ring,
//              so NO shfl latency sits on the state recurrence.
//   warps 1-3: far dot for chunk c+1 over old history (double-buffered smem).
//
// integ[n] = Sum_{l<=n} rk[l]*I_hist[n-l],  rk[l] = me[T-1-l].
// acc_lane(after step s) = far + cross + Sum_{u<=s} rk[lane-u]*I_u.
// At step s: integ_s = dt*( aP[s&3]  (shfl'd at s-4: all terms u<=s-4 + far)
//                         + nP[s&3]  (locally accumulated rk[3..0] terms) ).
// Critical carried chain: I -> bSI -> dI -> I  (pure register FMAs).
// ---------------------------------------------------------------------------
__global__ void __launch_bounds__(128, 1)
solver_kernel(const float* __restrict__ t,
              const float* __restrict__ y,
              const float* __restrict__ beta_p,
              const float* __restrict__ gamma_p,
              float* __restrict__ out)
{
    __shared__ __align__(16) float rkp[32 + T]; // rkp[32+m] = rk[m]; rkp[0..31]=0 pad
    __shared__ __align__(16) float ihp[32 + T]; // ih = ihp+32; ihp[0..31]=0 pad
    __shared__ float farbuf[2][3][32];          // double-buffered helper partials

    float* ih = ihp + 32;
    const int tid  = threadIdx.x;
    const int w    = tid >> 5;
    const int lane = tid & 31;

    // Cooperative init
    for (int i = tid; i < 32 + T; i += 128) rkp[i] = (i < 32) ? 0.0f : g_me[T - 1 - (i - 32)];
    for (int i = tid; i < 32 + T; i += 128) ihp[i] = 0.0f;
    if (tid < 192) (&farbuf[0][0][0])[tid] = 0.0f;

    const int   b     = blockIdx.x;
    const float dt    = t[0] - t[1];       // = 1/(T-1), positive
    const float beta  = beta_p[0];
    const float gamma = gamma_p[0];

    float S = y[b * 3 + 0];
    float I = y[b * 3 + 1];
    float R = y[b * 3 + 2];

    if (tid == 0) ih[0] = I;

    // solution[0] = y0 ; diff[T-1] = 0 (d_out is poisoned -> must be written)
    if (w == 0 && lane < 3) {
        float sv = (lane == 0) ? S : ((lane == 1) ? I : R);
        out[b * 3 + lane] = sv;
        out[(size_t)T * OSTRIDE + (T - 1) * OSTRIDE + b * 3 + lane] = 0.0f;
    }
    __syncthreads();

    const float* rk = rkp + 32;

    // Register-resident kernel taps.
    float tap[32], tapR[32];
#pragma unroll
    for (int s = 0; s < 32; ++s) tap[s]  = rkp[32 + lane - s];   // rk[lane-s], pad=0
#pragma unroll
    for (int u = 0; u < 32; ++u) tapR[u] = rk[lane + 32 - u];    // rk[lane+32-u]
    const float rq0 = rk[0], rq1 = rk[1], rq2 = rk[2], rq3 = rk[3]; // replicated scalars

    float* po_sol = out + b * 3 + lane;                       // solution rows
    float* po_dif = out + (size_t)T * OSTRIDE + b * 3 + lane; // diff rows

    // ---------------- main loop: chunks 0..30 (32 steps each) ---------------
    for (int c = 0; c < 31; ++c) {
        if (w == 0) {
            const int base = c << 5;
            // acc = far(old history, helpers) + cross(previous chunk, smem)
            float acc = farbuf[c & 1][0][lane] + farbuf[c & 1][1][lane]
                      + farbuf[c & 1][2][lane];
            {
                const float4* cv = (const float4*)(ih + base - 32); // pad zeros for c=0
#pragma unroll
                for (int q = 0; q < 8; ++q) {
                    const float4 v = cv[q];
                    acc = fmaf(tapR[4*q],     v.x, acc);
                    acc = fmaf(tapR[4*q + 1], v.y, acc);
                    acc = fmaf(tapR[4*q + 2], v.z, acc);
                    acc = fmaf(tapR[4*q + 3], v.w, acc);
                }
            }

            // Lookahead rings
            float aP[4], nP[4];
            nP[0] = 0.0f; nP[1] = 0.0f; nP[2] = 0.0f; nP[3] = 0.0f;
            aP[0] = __shfl_sync(FULL, acc, 0);
            aP[1] = __shfl_sync(FULL, acc, 1);
            aP[2] = __shfl_sync(FULL, acc, 2);
            aP[3] = __shfl_sync(FULL, acc, 3);

            float* ps = po_sol + base * OSTRIDE;
            float* pd = po_dif + base * OSTRIDE;

#pragma unroll
            for (int s = 0; s < 32; ++s) {
                // ring near-updates with I = I_s (compile-time guards)
                if (s + 3 <= 31) nP[(s + 3) & 3] = rq3 * I;                  // assign
                if (s + 2 <= 31) nP[(s + 2) & 3] = fmaf(rq2, I, nP[(s + 2) & 3]);
                if (s + 1 <= 31) nP[(s + 1) & 3] = fmaf(rq1, I, nP[(s + 1) & 3]);
                nP[s & 3] = fmaf(rq0, I, nP[s & 3]);

                const float integ = dt * (aP[s & 3] + nP[s & 3]);

                acc = fmaf(tap[s], I, acc);
                if (s + 4 <= 31) aP[(s + 4) & 3] = __shfl_sync(FULL, acc, s + 4);

                const float bSI = beta * S * I;
                const float gI  = gamma * I;
                const float dS  = integ - bSI;
                const float dI  = bSI - gI;
                const float dR  = gI - integ;
                S = fmaf(dS, dt, S);
                I = fmaf(dI, dt, I);
                R = fmaf(dR, dt, R);

                const float sv = (lane == 0) ? S  : ((lane == 1) ? I  : R);
                const float dv = (lane == 0) ? dS : ((lane == 1) ? dI : dR);
                if (lane < 3) ps[(s + 1) * OSTRIDE] = sv;   // predicated STG
                if (lane < 3) pd[s * OSTRIDE]       = dv;   // predicated STG
                ih[base + s + 1] = I;                       // all lanes, same addr
            }
        } else {
            // Helpers: far for chunk c+1 over history t < 32c.
            const int hw = w - 1;                           // 0..2
            float h0 = 0.0f, h1 = 0.0f, h2 = 0.0f, h3 = 0.0f;
            const float*  rf  = rk + ((c + 1) << 5) + lane; // rf[-t] = rk[32(c+1)+lane-t]
            const float4* ih4 = (const float4*)ih;
            const int n4 = (c << 5) >> 2;                   // 8c float4 groups
            for (int q = hw; q < n4; q += 3) {
                const float4 iv = ih4[q];
                const int tq = q << 2;
                h0 = fmaf(rf[-tq],       iv.x, h0);
                h1 = fmaf(rf[-(tq + 1)], iv.y, h1);
                h2 = fmaf(rf[-(tq + 2)], iv.z, h2);
                h3 = fmaf(rf[-(tq + 3)], iv.w, h3);
            }
            farbuf[(c + 1) & 1][hw][lane] = (h0 + h1) + (h2 + h3);
        }
        __syncthreads();   // farbuf handoff + ih visibility for next chunk
    }

    // ---------------- final chunk c=31: steps 992..1022 (31 steps) ----------
    if (w == 0) {
        const int base = 31 << 5;   // 992
        float acc = farbuf[1][0][lane] + farbuf[1][1][lane] + farbuf[1][2][lane];
        {
            const float4* cv = (const float4*)(ih + base - 32);
#pragma unroll
            for (int q = 0; q < 8; ++q) {
                const float4 v = cv[q];
                acc = fmaf(tapR[4*q],     v.x, acc);
                acc = fmaf(tapR[4*q + 1], v.y, acc);
                acc = fmaf(tapR[4*q + 2], v.z, acc);
                acc = fmaf(tapR[4*q + 3], v.w, acc);
            }
        }

        float aP[4], nP[4];
        nP[0] = 0.0f; nP[1] = 0.0f; nP[2] = 0.0f; nP[3] = 0.0f;
        aP[0] = __shfl_sync(FULL, acc, 0);
        aP[1] = __shfl_sync(FULL, acc, 1);
        aP[2] = __shfl_sync(FULL, acc, 2);
        aP[3] = __shfl_sync(FULL, acc, 3);

        float* ps = po_sol + base * OSTRIDE;
        float* pd = po_dif + base * OSTRIDE;

#pragma unroll
        for (int s = 0; s < 31; ++s) {
            if (s + 3 <= 30) nP[(s + 3) & 3] = rq3 * I;
            if (s + 2 <= 30) nP[(s + 2) & 3] = fmaf(rq2, I, nP[(s + 2) & 3]);
            if (s + 1 <= 30) nP[(s + 1) & 3] = fmaf(rq1, I, nP[(s + 1) & 3]);
            nP[s & 3] = fmaf(rq0, I, nP[s & 3]);

            const float integ = dt * (aP[s & 3] + nP[s & 3]);

            acc = fmaf(tap[s], I, acc);
            if (s + 4 <= 30) aP[(s + 4) & 3] = __shfl_sync(FULL, acc, s + 4);

            const float bSI = beta * S * I;
            const float gI  = gamma * I;
            const float dS  = integ - bSI;
            const float dI  = bSI - gI;
            const float dR  = gI - integ;
            S = fmaf(dS, dt, S);
            I = fmaf(dI, dt, I);
            R = fmaf(dR, dt, R);

            const float sv = (lane == 0) ? S  : ((lane == 1) ? I  : R);
            const float dv = (lane == 0) ? dS : ((lane == 1) ? dI : dR);
            if (lane < 3) ps[(s + 1) * OSTRIDE] = sv;
            if (lane < 3) pd[s * OSTRIDE]       = dv;
        }
    }
}

// ---------------------------------------------------------------------------
// Launch: two kernels, stream-ordered, graph-capturable, allocation-free.
// Input order (metadata): t, y, w1, b1, w2, b2, w3, b3, w4, b4, beta, gamma
// Output: [solution (T,B,3) | diff (T,B,3)] float32
// ---------------------------------------------------------------------------
extern "C" void kernel_launch(void* const* d_in, const int* in_sizes, int n_in,
                              void* d_out, int out_size)
{
    const float* t  = (const float*)d_in[0];
    const float* y  = (const float*)d_in[1];
    const float* w1 = (const float*)d_in[2];
    const float* b1 = (const float*)d_in[3];
    const float* w2 = (const float*)d_in[4];
    const float* b2 = (const float*)d_in[5];
    const float* w3 = (const float*)d_in[6];
    const float* b3 = (const float*)d_in[7];
    const float* w4 = (const float*)d_in[8];
    const float* b4 = (const float*)d_in[9];
    const float* be = (const float*)d_in[10];
    const float* ga = (const float*)d_in[11];
    float* out = (float*)d_out;

    mlp_kernel<<<4, 256>>>(t, w1, b1, w2, b2, w3, b3, w4, b4);
    solver_kernel<<<B, 128>>>(t, y, be, ga, out);
}

// round 8
// speedup vs baseline: 2.0960x; 1.0112x over previous
#include <cuda_runtime.h>
#include <math.h>

// Problem constants (fixed by the reference)
#define T  1024
#define B  256
#define H  20
#define FULL 0xffffffffu
#define OSTRIDE (B * 3)          // 768 floats between consecutive time rows

// Memory kernel me[t] = sigmoid(MLP(t))
__device__ float g_me[T];

// ---------------------------------------------------------------------------
// Kernel 1: tiny MLP over the T time points. One thread per time point.
// ---------------------------------------------------------------------------
__global__ void mlp_kernel(const float* __restrict__ t,
                           const float* __restrict__ w1, const float* __restrict__ b1,
                           const float* __restrict__ w2, const float* __restrict__ b2,
                           const float* __restrict__ w3, const float* __restrict__ b3,
                           const float* __restrict__ w4, const float* __restrict__ b4)
{
    int i = blockIdx.x * blockDim.x + threadIdx.x;
    if (i >= T) return;
    float x = t[i];

    float h1[H], h2[H], h3[H];
#pragma unroll
    for (int j = 0; j < H; ++j) h1[j] = tanhf(x * w1[j] + b1[j]);

#pragma unroll
    for (int j = 0; j < H; ++j) {
        float s = b2[j];
#pragma unroll
        for (int k = 0; k < H; ++k) s += h1[k] * w2[k * H + j];
        h2[j] = tanhf(s);
    }

#pragma unroll
    for (int j = 0; j < H; ++j) {
        float s = b3[j];
#pragma unroll
        for (int k = 0; k < H; ++k) s += h2[k] * w3[k * H + j];
        h3[j] = tanhf(s);
    }

    float s = b4[0];
#pragma unroll
    for (int k = 0; k < H; ++k) s += h3[k] * w4[k];

    g_me[i] = 1.0f / (1.0f + expf(-s));   // sigmoid
}

// ---------------------------------------------------------------------------
// Kernel 2: TWO batch elements per block (128 blocks -> ONE wave on 148 SMs).
//   warp 0: near chain for batch b0      warp 1: near chain for batch b1
//   warps 2-4: far helpers for b0        warps 5-7: far helpers for b1
// Near chain: 32-step chunks with 4-step lookahead broadcast (shfl result
// consumed 4 steps after issue; last 4 near taps accumulated redundantly).
// Helpers: far dot for chunk c+1 over old history; manually 4x-unrolled with
// 16 independent accumulators so LDS latency is pipelined.
// ---------------------------------------------------------------------------
__global__ void __launch_bounds__(256, 1)
solver_kernel(const float* __restrict__ t,
              const float* __restrict__ y,
              const float* __restrict__ beta_p,
              const float* __restrict__ gamma_p,
              float* __restrict__ out)
{
    __shared__ __align__(16) float rkp[32 + T];     // rk[m]=me[T-1-m]; rkp[0..31]=0 pad
    __shared__ __align__(16) float ihp[2][32 + T];  // per-half I history (+32 zero pad)
    __shared__ float farbuf[2][2][3][32];           // [half][parity][hw][lane]

    const int tid  = threadIdx.x;
    const int w    = tid >> 5;
    const int lane = tid & 31;

    // Roles
    const bool nearW = (w < 2);
    const int  half  = nearW ? w : ((w - 2) / 3);   // 0 or 1
    const int  hw    = nearW ? 0 : ((w - 2) % 3);   // helper index 0..2

    // Cooperative init
    for (int i = tid; i < 32 + T; i += 256) rkp[i] = (i < 32) ? 0.0f : g_me[T - 1 - (i - 32)];
    for (int i = tid; i < 2 * (32 + T); i += 256) (&ihp[0][0])[i] = 0.0f;
    for (int i = tid; i < 384; i += 256) (&farbuf[0][0][0][0])[i] = 0.0f;

    const int   b     = blockIdx.x * 2 + half;
    const float dt    = t[0] - t[1];       // = 1/(T-1), positive
    const float beta  = beta_p[0];
    const float gamma = gamma_p[0];

    float* ih = ihp[half] + 32;

    float S = y[b * 3 + 0];
    float I = y[b * 3 + 1];
    float R = y[b * 3 + 2];

    if (nearW && lane == 0) ih[0] = I;

    // solution[0] = y0 ; diff[T-1] = 0 (d_out is poisoned -> must be written)
    if (nearW && lane < 3) {
        float sv = (lane == 0) ? S : ((lane == 1) ? I : R);
        out[b * 3 + lane] = sv;
        out[(size_t)T * OSTRIDE + (T - 1) * OSTRIDE + b * 3 + lane] = 0.0f;
    }
    __syncthreads();

    const float* rk = rkp + 32;

    // Register-resident kernel taps (used by near warps).
    float tap[32], tapR[32];
#pragma unroll
    for (int s = 0; s < 32; ++s) tap[s]  = rkp[32 + lane - s];   // rk[lane-s], pad=0
#pragma unroll
    for (int u = 0; u < 32; ++u) tapR[u] = rk[lane + 32 - u];    // rk[lane+32-u]
    const float rq0 = rk[0], rq1 = rk[1], rq2 = rk[2], rq3 = rk[3];

    float* po_sol = out + b * 3 + lane;                       // solution rows
    float* po_dif = out + (size_t)T * OSTRIDE + b * 3 + lane; // diff rows

    // ---------------- main loop: chunks 0..30 (32 steps each) ---------------
    for (int c = 0; c < 31; ++c) {
        if (nearW) {
            const int base = c << 5;
            float acc = farbuf[half][c & 1][0][lane] + farbuf[half][c & 1][1][lane]
                      + farbuf[half][c & 1][2][lane];
            {
                const float4* cv = (const float4*)(ih + base - 32); // pad zeros for c=0
#pragma unroll
                for (int q = 0; q < 8; ++q) {
                    const float4 v = cv[q];
                    acc = fmaf(tapR[4*q],     v.x, acc);
                    acc = fmaf(tapR[4*q + 1], v.y, acc);
                    acc = fmaf(tapR[4*q + 2], v.z, acc);
                    acc = fmaf(tapR[4*q + 3], v.w, acc);
                }
            }

            // Lookahead rings
            float aP[4], nP[4];
            nP[0] = 0.0f; nP[1] = 0.0f; nP[2] = 0.0f; nP[3] = 0.0f;
            aP[0] = __shfl_sync(FULL, acc, 0);
            aP[1] = __shfl_sync(FULL, acc, 1);
            aP[2] = __shfl_sync(FULL, acc, 2);
            aP[3] = __shfl_sync(FULL, acc, 3);

            float* ps = po_sol + base * OSTRIDE;
            float* pd = po_dif + base * OSTRIDE;

#pragma unroll
            for (int s = 0; s < 32; ++s) {
                if (s + 3 <= 31) nP[(s + 3) & 3] = rq3 * I;
                if (s + 2 <= 31) nP[(s + 2) & 3] = fmaf(rq2, I, nP[(s + 2) & 3]);
                if (s + 1 <= 31) nP[(s + 1) & 3] = fmaf(rq1, I, nP[(s + 1) & 3]);
                nP[s & 3] = fmaf(rq0, I, nP[s & 3]);

                const float integ = dt * (aP[s & 3] + nP[s & 3]);

                acc = fmaf(tap[s], I, acc);
                if (s + 4 <= 31) aP[(s + 4) & 3] = __shfl_sync(FULL, acc, s + 4);

                const float bSI = beta * S * I;
                const float gI  = gamma * I;
                const float dS  = integ - bSI;
                const float dI  = bSI - gI;
                const float dR  = gI - integ;
                S = fmaf(dS, dt, S);
                I = fmaf(dI, dt, I);
                R = fmaf(dR, dt, R);

                const float sv = (lane == 0) ? S  : ((lane == 1) ? I  : R);
                const float dv = (lane == 0) ? dS : ((lane == 1) ? dI : dR);
                if (lane < 3) ps[(s + 1) * OSTRIDE] = sv;   // predicated STG
                if (lane < 3) pd[s * OSTRIDE]       = dv;   // predicated STG
                ih[base + s + 1] = I;                       // all lanes, same addr
            }
        } else {
            // Helpers: far for chunk c+1 over history t < 32c, 4x unrolled,
            // 16 independent accumulators (all indices compile-time).
            float hs[4][4];
#pragma unroll
            for (int u = 0; u < 4; ++u)
#pragma unroll
                for (int v = 0; v < 4; ++v) hs[u][v] = 0.0f;

            const float*  rf  = rk + ((c + 1) << 5) + lane; // rf[-t] = rk[32(c+1)+lane-t]
            const float4* ih4 = (const float4*)ih;
            const int n4 = (c << 5) >> 2;                   // 8c float4 groups
            int q = hw;
            for (; q + 9 < n4; q += 12) {
#pragma unroll
                for (int u = 0; u < 4; ++u) {
                    const int qq = q + 3 * u;
                    const float4 iv = ih4[qq];
                    const int tq = qq << 2;
                    hs[u][0] = fmaf(rf[-tq],       iv.x, hs[u][0]);
                    hs[u][1] = fmaf(rf[-(tq + 1)], iv.y, hs[u][1]);
                    hs[u][2] = fmaf(rf[-(tq + 2)], iv.z, hs[u][2]);
                    hs[u][3] = fmaf(rf[-(tq + 3)], iv.w, hs[u][3]);
                }
            }
            for (; q < n4; q += 3) {
                const float4 iv = ih4[q];
                const int tq = q << 2;
                hs[0][0] = fmaf(rf[-tq],       iv.x, hs[0][0]);
                hs[0][1] = fmaf(rf[-(tq + 1)], iv.y, hs[0][1]);
                hs[0][2] = fmaf(rf[-(tq + 2)], iv.z, hs[0][2]);
                hs[0][3] = fmaf(rf[-(tq + 3)], iv.w, hs[0][3]);
            }
            const float r0 = (hs[0][0] + hs[0][1]) + (hs[0][2] + hs[0][3]);
            const float r1 = (hs[1][0] + hs[1][1]) + (hs[1][2] + hs[1][3]);
            const float r2 = (hs[2][0] + hs[2][1]) + (hs[2][2] + hs[2][3]);
            const float r3 = (hs[3][0] + hs[3][1]) + (hs[3][2] + hs[3][3]);
            farbuf[half][(c + 1) & 1][hw][lane] = (r0 + r1) + (r2 + r3);
        }
        __syncthreads();   // farbuf handoff + ih visibility for next chunk
    }

    // ---------------- final chunk c=31: steps 992..1022 (31 steps) ----------
    if (nearW) {
        const int base = 31 << 5;   // 992
        float acc = farbuf[half][1][0][lane] + farbuf[half][1][1][lane]
                  + farbuf[half][1][2][lane];
        {
            const float4* cv = (const float4*)(ih + base - 32);
#pragma unroll
            for (int q = 0; q < 8; ++q) {
                const float4 v = cv[q];
                acc = fmaf(tapR[4*q],     v.x, acc);
                acc = fmaf(tapR[4*q + 1], v.y, acc);
                acc = fmaf(tapR[4*q + 2], v.z, acc);
                acc = fmaf(tapR[4*q + 3], v.w, acc);
            }
        }

        float aP[4], nP[4];
        nP[0] = 0.0f; nP[1] = 0.0f; nP[2] = 0.0f; nP[3] = 0.0f;
        aP[0] = __shfl_sync(FULL, acc, 0);
        aP[1] = __shfl_sync(FULL, acc, 1);
        aP[2] = __shfl_sync(FULL, acc, 2);
        aP[3] = __shfl_sync(FULL, acc, 3);

        float* ps = po_sol + base * OSTRIDE;
        float* pd = po_dif + base * OSTRIDE;

#pragma unroll
        for (int s = 0; s < 31; ++s) {
            if (s + 3 <= 30) nP[(s + 3) & 3] = rq3 * I;
            if (s + 2 <= 30) nP[(s + 2) & 3] = fmaf(rq2, I, nP[(s + 2) & 3]);
            if (s + 1 <= 30) nP[(s + 1) & 3] = fmaf(rq1, I, nP[(s + 1) & 3]);
            nP[s & 3] = fmaf(rq0, I, nP[s & 3]);

            const float integ = dt * (aP[s & 3] + nP[s & 3]);

            acc = fmaf(tap[s], I, acc);
            if (s + 4 <= 30) aP[(s + 4) & 3] = __shfl_sync(FULL, acc, s + 4);

            const float bSI = beta * S * I;
            const float gI  = gamma * I;
            const float dS  = integ - bSI;
            const float dI  = bSI - gI;
            const float dR  = gI - integ;
            S = fmaf(dS, dt, S);
            I = fmaf(dI, dt, I);
            R = fmaf(dR, dt, R);

            const float sv = (lane == 0) ? S  : ((lane == 1) ? I  : R);
            const float dv = (lane == 0) ? dS : ((lane == 1) ? dI : dR);
            if (lane < 3) ps[(s + 1) * OSTRIDE] = sv;
            if (lane < 3) pd[s * OSTRIDE]       = dv;
        }
    }
}

// ---------------------------------------------------------------------------
// Launch: two kernels, stream-ordered, graph-capturable, allocation-free.
// Input order (metadata): t, y, w1, b1, w2, b2, w3, b3, w4, b4, beta, gamma
// Output: [solution (T,B,3) | diff (T,B,3)] float32
// ---------------------------------------------------------------------------
extern "C" void kernel_launch(void* const* d_in, const int* in_sizes, int n_in,
                              void* d_out, int out_size)
{
    const float* t  = (const float*)d_in[0];
    const float* y  = (const float*)d_in[1];
    const float* w1 = (const float*)d_in[2];
    const float* b1 = (const float*)d_in[3];
    const float* w2 = (const float*)d_in[4];
    const float* b2 = (const float*)d_in[5];
    const float* w3 = (const float*)d_in[6];
    const float* b3 = (const float*)d_in[7];
    const float* w4 = (const float*)d_in[8];
    const float* b4 = (const float*)d_in[9];
    const float* be = (const float*)d_in[10];
    const float* ga = (const float*)d_in[11];
    float* out = (float*)d_out;

    mlp_kernel<<<4, 256>>>(t, w1, b1, w2, b2, w3, b3, w4, b4);
    solver_kernel<<<B / 2, 256>>>(t, y, be, ga, out);
}